// round 15
// baseline (speedup 1.0000x reference)
#include <cuda_runtime.h>
#include <cstddef>

#define Bb 8
#define Tt 2048
#define Dd 512
#define Hh 512
#define FOURH 2048
#define GRID_R 128
#define DOM_BLKS 16          // blocks per sync domain (1 batch per domain)

typedef unsigned long long u64;

// ---------------- scratch (static device globals: allocation-free) ----------------
__device__ float g_wx[(size_t)Bb * Tt * FOURH];   // 128 MiB: precomputed x @ W^T + b
__device__ float g_h[2][Bb * Hh];                 // double-buffered hidden state
__device__ unsigned g_cnt8[8 * 32];               // 8 per-domain counters, 128B apart

// ---------------- packed f32x2 helpers (b64 regs via "l" constraint) ----------------
__device__ __forceinline__ void fma2(u64 &acc, u64 a, u64 b) {
    asm("fma.rn.f32x2 %0, %1, %2, %0;" : "+l"(acc) : "l"(a), "l"(b));
}
__device__ __forceinline__ void unpack2(u64 v, float &lo, float &hi) {
    asm("mov.b64 {%0, %1}, %2;" : "=f"(lo), "=f"(hi) : "l"(v));
}

// ---------------- scoped sync primitives ----------------
__device__ __forceinline__ void cnt_arrive_release(unsigned* p) {
    asm volatile("red.release.gpu.global.add.u32 [%0], %1;"
                 :: "l"(p), "r"(1u) : "memory");
}
__device__ __forceinline__ unsigned ld_acquire(const unsigned* p) {
    unsigned v;
    asm volatile("ld.acquire.gpu.global.u32 %0, [%1];"
                 : "=r"(v) : "l"(p) : "memory");
    return v;
}

// ---------------- fast gate math (MUFU-based) ----------------
__device__ __forceinline__ float sigm_f(float x) {
    return __fdividef(1.f, 1.f + __expf(-x));
}
__device__ __forceinline__ float tanh_f(float x) {
    float e = __expf(2.f * x);
    return 1.f - __fdividef(2.f, e + 1.f);
}

// ---------------- tf32 helpers ----------------
__device__ __forceinline__ unsigned tf32cvt(float f) {
    unsigned r; asm("cvt.rna.tf32.f32 %0, %1;" : "=r"(r) : "f"(f)); return r;
}
__device__ __forceinline__ void mma_tf32(float* d, const unsigned* a, const unsigned* b) {
    asm("mma.sync.aligned.m16n8k8.row.col.f32.tf32.tf32.f32 "
        "{%0,%1,%2,%3}, {%4,%5,%6,%7}, {%8,%9}, {%0,%1,%2,%3};"
        : "+f"(d[0]), "+f"(d[1]), "+f"(d[2]), "+f"(d[3])
        : "r"(a[0]), "r"(a[1]), "r"(a[2]), "r"(a[3]), "r"(b[0]), "r"(b[1]));
}

// =====================================================================
// Kernel 1 (tf32): Wx = x @ W_w^T + W_b  (R14 version; ~456us, kept)
// =====================================================================
__global__ void __launch_bounds__(256, 2) gemm_wx_tf32_kernel(
    const float* __restrict__ x, const float* __restrict__ Ww,
    const float* __restrict__ Wb)
{
    __shared__ __align__(16) unsigned As[2][128][20];
    __shared__ __align__(16) unsigned Bs[2][128][20];

    const int tid  = threadIdx.x;
    const int w    = tid >> 5;
    const int lane = tid & 31;
    const int g    = lane >> 2;
    const int tig  = lane & 3;
    const int wm   = w >> 1;
    const int wn   = w & 1;
    const int m0   = blockIdx.y * 128;
    const int n0   = blockIdx.x * 128;

    const int lr = tid >> 1;
    const int lh = tid & 1;

    float acc[2][8][4];
    #pragma unroll
    for (int mt = 0; mt < 2; mt++)
        #pragma unroll
        for (int nt = 0; nt < 8; nt++)
            #pragma unroll
            for (int c = 0; c < 4; c++) acc[mt][nt][c] = 0.f;

    float4 ra[2], rb[2];
    {
        const float* pa = &x [(size_t)(m0 + lr) * 512 + lh * 8];
        const float* pb = &Ww[(size_t)(n0 + lr) * 512 + lh * 8];
        ra[0] = *(const float4*)(pa);     ra[1] = *(const float4*)(pa + 4);
        rb[0] = *(const float4*)(pb);     rb[1] = *(const float4*)(pb + 4);
    }

    for (int chunk = 0; chunk < 32; chunk++) {
        const int buf = chunk & 1;
        {
            const float* f  = (const float*)ra;
            const float* fw = (const float*)rb;
            const int base = lh * 8;
            uint4 v0 = make_uint4(tf32cvt(f[0]), tf32cvt(f[4]), tf32cvt(f[1]), tf32cvt(f[5]));
            uint4 v1 = make_uint4(tf32cvt(f[2]), tf32cvt(f[6]), tf32cvt(f[3]), tf32cvt(f[7]));
            *(uint4*)&As[buf][lr][base]     = v0;
            *(uint4*)&As[buf][lr][base + 4] = v1;
            uint4 w0 = make_uint4(tf32cvt(fw[0]), tf32cvt(fw[4]), tf32cvt(fw[1]), tf32cvt(fw[5]));
            uint4 w1 = make_uint4(tf32cvt(fw[2]), tf32cvt(fw[6]), tf32cvt(fw[3]), tf32cvt(fw[7]));
            *(uint4*)&Bs[buf][lr][base]     = w0;
            *(uint4*)&Bs[buf][lr][base + 4] = w1;
        }
        __syncthreads();

        if (chunk < 31) {
            const int kc = (chunk + 1) * 16;
            const float* pa = &x [(size_t)(m0 + lr) * 512 + kc + lh * 8];
            const float* pb = &Ww[(size_t)(n0 + lr) * 512 + kc + lh * 8];
            ra[0] = *(const float4*)(pa);     ra[1] = *(const float4*)(pa + 4);
            rb[0] = *(const float4*)(pb);     rb[1] = *(const float4*)(pb + 4);
        }

        #pragma unroll
        for (int s = 0; s < 2; s++) {
            const int koff = 8 * s + 2 * tig;
            unsigned afrag[2][4];
            #pragma unroll
            for (int mt = 0; mt < 2; mt++) {
                const int rowA = wm * 32 + mt * 16 + g;
                uint2 p1 = *(const uint2*)&As[buf][rowA][koff];
                uint2 p2 = *(const uint2*)&As[buf][rowA + 8][koff];
                afrag[mt][0] = p1.x; afrag[mt][1] = p2.x;
                afrag[mt][2] = p1.y; afrag[mt][3] = p2.y;
            }
            #pragma unroll
            for (int nt = 0; nt < 8; nt++) {
                const int rowB = wn * 64 + nt * 8 + g;
                uint2 bp = *(const uint2*)&Bs[buf][rowB][koff];
                unsigned bfrag[2] = { bp.x, bp.y };
                mma_tf32(acc[0][nt], afrag[0], bfrag);
                mma_tf32(acc[1][nt], afrag[1], bfrag);
            }
        }
    }

    #pragma unroll
    for (int nt = 0; nt < 8; nt++) {
        const int colD = n0 + wn * 64 + nt * 8 + 2 * tig;
        const float2 wb2 = *(const float2*)&Wb[colD];
        #pragma unroll
        for (int mt = 0; mt < 2; mt++) {
            const int rowD = m0 + wm * 32 + mt * 16 + g;
            float2 lo = make_float2(acc[mt][nt][0] + wb2.x, acc[mt][nt][1] + wb2.y);
            float2 hi = make_float2(acc[mt][nt][2] + wb2.x, acc[mt][nt][3] + wb2.y);
            *(float2*)&g_wx[(size_t)rowD * FOURH + colD]       = lo;
            *(float2*)&g_wx[(size_t)(rowD + 8) * FOURH + colD] = hi;
        }
    }
}

// =====================================================================
// Kernel 2: persistent recurrent sLSTM, 8 SINGLE-BATCH sync domains.
// Domain d = blk>>4 owns batch d; 16 blocks per domain.
// Block owns 32 units j0 = (blk&15)*32.
// Warp w owns 2 units via half-warps: half hf = lane>>4 -> unit 2w+hf.
// Half-warp lane L=lane&15 owns cols 4L + 64q (q=0..7); computes all 4
// gates (u[4][8-as-halves] = 64 regs, acc[4] = 8 regs, 64 fma2/lane).
// Fold d8/d4 + scalar d2/d1 -> lane slot gate=(L>>2)&3; parallel
// activations; gather at L==0 (lanes 0,16) updates c, stores h.
// Protocol identical to R12: tid0 poll, 3 syncs, 1 RED/block/step.
// =====================================================================
__global__ void __launch_bounds__(512) lstm_rec_kernel(
    const float* __restrict__ Uw, const float* __restrict__ Ub,
    const float* __restrict__ alpha, float* __restrict__ out)
{
    __shared__ __align__(16) float h_s[Hh];       // 2 KB: this domain's single h row

    const int tid  = threadIdx.x;
    const int w    = tid >> 5;
    const int lane = tid & 31;
    const int hf   = lane >> 4;     // half-warp 0/1
    const int L    = lane & 15;     // lane within half
    const int blk  = blockIdx.x;
    const int dom  = blk >> 4;      // sync domain 0..7 = batch
    const int j0   = (blk & 15) * 32;
    const int jg   = j0 + 2 * w + hf;   // this half-warp's hidden unit
    const int B    = dom;               // this domain's batch

    const int g_l  = (L >> 2) & 3;  // this lane's gate slot

    // U_w register-resident: rows (g, jg), lane cols 4L + 64q, q=0..7
    ulonglong2 u[4][4];             // [gate][q-pair]: q = 2*qq and 2*qq+1 packed? no:
    // store as 4 gates x 4 ulonglong2-pairs covering q=0..7 via two .x/.y? Keep simple:
    // u2[g][q] for q=0..7 as ulonglong2 would be 128 regs; instead each ulonglong2 holds
    // 4 floats = cols 4L+64q .. +3, so we need 8 of them per gate = 64 regs total for
    // 4 gates only if each is 16B... 4 gates x 8 q x 16B = 512B = 128 regs. Too many.
    // Solution: halve to u64 (2 floats): cols 2 per load? That doubles fma2 ops? No:
    // fma2 consumes 2 cols per op either way. Use u64 u8[4][8]: 4*8*2 = 64 regs, and
    // lane owns cols 2L' scheme: cols 2*L + 32*q? covers 16 lanes*2*16q... Let's use:
    // lane owns col-pairs {2L + 32q : q=0..15}? 16 q values -> 64 regs, 64 fma2. OK.
    u64 uu[4][16];
    #pragma unroll
    for (int g = 0; g < 4; g++)
        #pragma unroll
        for (int q = 0; q < 16; q++)
            uu[g][q] = *(const u64*)&Uw[(size_t)(g * Hh + jg) * Hh + 32 * q + 2 * L];

    const float ub_r    = Ub[g_l * Hh + jg];
    const float alpha_r = alpha[jg];
    float c_st = 0.f;               // live in lanes 0 and 16

    unsigned* const my_cnt = &g_cnt8[dom * 32];

    // publish h0 = 0: warp 0 zeroes this block's 32 floats (32 units, batch B)
    if (w == 0) {
        g_h[0][B * Hh + j0 + lane] = 0.f;
        __syncwarp();
        if (lane == 0) cnt_arrive_release(my_cnt);
    }
    __syncthreads();

    for (int t = 0; t < Tt; ++t) {
        // prefetch Wx_t for this lane's (gate, unit, batch) slot
        const float wx = __ldg(&g_wx[((size_t)B * Tt + t) * FOURH + g_l * Hh + jg]);

        // ---- domain barrier: all 16 blocks of this domain published h_t
        if (tid == 0) {
            const unsigned tgt = (unsigned)DOM_BLKS * (unsigned)(t + 1);
            int spins = 0;
            while (ld_acquire(my_cnt) < tgt) {
                if (++spins > 64) __nanosleep(64);
            }
        }
        __syncthreads();

        // ---- stage this domain's h row (2 KB; L2-only loads)
        if (tid < 128) {
            const float4* src = (const float4*)&g_h[t & 1][B * Hh];
            ((float4*)&h_s[0])[tid] = __ldcg(&src[tid]);
        }
        __syncthreads();

        // ---- dots: 4 gates over full 512 cols (u64 col-pairs from smem)
        u64 acc[4];
        #pragma unroll
        for (int g = 0; g < 4; g++) acc[g] = 0ull;
        #pragma unroll
        for (int q = 0; q < 16; q++) {
            const u64 h2 = *(const u64*)&h_s[32 * q + 2 * L];
            #pragma unroll
            for (int g = 0; g < 4; g++) fma2(acc[g], uu[g][q], h2);
        }

        // collapse pair halves -> v[g]
        float v[4];
        #pragma unroll
        for (int g = 0; g < 4; g++) {
            float lo, hi; unpack2(acc[g], lo, hi);
            v[g] = lo + hi;
        }

        // fold within 16-lane half: d8 (4->2), d4 (2->1), then scalar d2,d1.
        // Lane L ends with the 16-lane total for gate (L>>2)&3.
        {
            const bool up8 = (L & 8) != 0;
            #pragma unroll
            for (int i = 0; i < 2; i++) {
                float a = v[i], bv = v[i + 2];
                float mine = up8 ? bv : a, oth = up8 ? a : bv;
                v[i] = mine + __shfl_xor_sync(0xffffffffu, oth, 8);
            }
            const bool up4 = (L & 4) != 0;
            {
                float a = v[0], bv = v[1];
                float mine = up4 ? bv : a, oth = up4 ? a : bv;
                v[0] = mine + __shfl_xor_sync(0xffffffffu, oth, 4);
            }
            v[0] += __shfl_xor_sync(0xffffffffu, v[0], 2);
            v[0] += __shfl_xor_sync(0xffffffffu, v[0], 1);
        }

        // parallel activations: each lane activates its gate slot
        const float z = v[0] + wx + ub_r;
        const float a = (g_l == 3) ? tanh_f(z) : sigm_f(z);

        // gather i/f/o/g at L==0 (lanes 0 and 16); update c; store h
        const float a_f = __shfl_down_sync(0xffffffffu, a, 4);
        const float a_o = __shfl_down_sync(0xffffffffu, a, 8);
        const float a_g = __shfl_down_sync(0xffffffffu, a, 12);
        float hv = 0.f;
        if (L == 0) {
            c_st = alpha_r * (a_f * c_st + a * a_g);
            hv = a_o * tanh_f(c_st);
            g_h[(t + 1) & 1][B * Hh + jg] = hv;
        }

        // ---- all warps' h stores done -> single release-RED per block
        __syncthreads();
        if (tid == 0) cnt_arrive_release(my_cnt);

        // off-critical-path stores (kernel-end fence covers visibility)
        if (L == 0) {
            out[((size_t)B * Tt + t) * Hh + jg] = hv;
            if (t == Tt - 1) {
                out[(size_t)Bb * Tt * Hh + B * Hh + jg] = hv;                      // final h
                out[(size_t)Bb * Tt * Hh + (size_t)Bb * Hh + B * Hh + jg] = c_st;  // final c
            }
        }
    }

    // domain's slice-0 block resets its counter once all arrivals landed
    if ((blk & 15) == 0 && tid == 0) {
        const unsigned fin = (unsigned)DOM_BLKS * (unsigned)(Tt + 1);
        int spins = 0;
        while (ld_acquire(my_cnt) < fin) {
            if (++spins > 64) __nanosleep(128);
        }
        *my_cnt = 0u;
    }
}

// =====================================================================
extern "C" void kernel_launch(void* const* d_in, const int* in_sizes, int n_in,
                              void* d_out, int out_size)
{
    const float* x     = (const float*)d_in[0];
    const float* Ww    = (const float*)d_in[1];
    const float* Wb    = (const float*)d_in[2];
    const float* Uw    = (const float*)d_in[3];
    const float* Ub    = (const float*)d_in[4];
    const float* alpha = (const float*)d_in[5];
    float* out = (float*)d_out;

    dim3 ggrid(FOURH / 128, (Bb * Tt) / 128);   // 16 x 128
    gemm_wx_tf32_kernel<<<ggrid, 256>>>(x, Ww, Wb);
    lstm_rec_kernel<<<GRID_R, 512>>>(Uw, Ub, alpha, out);
}